// round 5
// baseline (speedup 1.0000x reference)
#include <cuda_runtime.h>
#include <cstddef>

// ---------------- problem constants ----------------
#define BATCH 8
#define NCLS 80
#define ATOT 22743            // 76*76*3 + 38*38*3 + 19*19*3
#define NFLAT (ATOT * NCLS)   // 1,819,440 per batch
#define PRE_NMS 400
#define MAX_DET 100

// ---------------- static scratch (no runtime allocs allowed) ----------------
__device__ float g_x[46208 * 256];                         // tower activations (max level 0), 47MB
__device__ float g_boxes[BATCH * ATOT * 4];                // decoded boxes
__device__ float g_scores[(size_t)BATCH * NFLAT];          // decoded scores, 58MB
__device__ unsigned g_hist1[BATCH * 4096];
__device__ unsigned g_hist2[BATCH * 4096];
__device__ unsigned g_b1[BATCH];
__device__ unsigned g_prefix1[BATCH];
__device__ unsigned g_pivot[BATCH];
__device__ unsigned g_cnt[BATCH];
__device__ unsigned long long g_cand[BATCH * 8192];

__constant__ float c_anchors[3][3][2] = {
    {{12.f, 16.f}, {19.f, 36.f}, {40.f, 28.f}},
    {{36.f, 75.f}, {76.f, 55.f}, {72.f, 146.f}},
    {{142.f, 110.f}, {192.f, 243.f}, {459.f, 401.f}}};

__device__ __forceinline__ float sigmoidf_(float x) { return 1.0f / (1.0f + expf(-x)); }

// ---------------- init ----------------
__global__ void zero_misc() {
    int i = blockIdx.x * blockDim.x + threadIdx.x;
    if (i < BATCH * 4096) { g_hist1[i] = 0u; g_hist2[i] = 0u; }
    if (i < BATCH) {
        g_cnt[i] = 0u;
        g_b1[i] = 0u;
        g_prefix1[i] = 0u;
        g_pivot[i] = 0u;
    }
}

// ---------------- fused conv3x3 + scale/bias + leaky-relu ----------------
// Implicit-GEMM: M = BATCH*H*H pixels, N = COUT, K = 9*CIN.
// BM=128, BN=128, BK=16, 256 threads, 8x8 microtile, double-buffered smem.
// No min-blocks cap: let ptxas use ~165 regs so nothing spills (R4 lesson:
// the 128-reg cap from __launch_bounds__(256,2) caused local spills that
// held fma at 53.7%).
template <int CIN, int COUT, int HH>
__global__ __launch_bounds__(256) void conv3x3(const float* __restrict__ in,
                                               const float* __restrict__ w,
                                               const float* __restrict__ gamma,
                                               const float* __restrict__ beta) {
    constexpr int M = BATCH * HH * HH;
    constexpr int KTOT = 9 * CIN;
    constexpr int NT = KTOT / 16;
    __shared__ float As[2][16][132];  // [buf][k][m]
    __shared__ float Bs[2][16][132];  // [buf][k][n]

    const int tid = threadIdx.x;
    const int bm0 = blockIdx.x * 128;
    const int bn0 = blockIdx.y * 128;

    // A-load per-thread coords: 2 float4 loads, row m = l*64 + tid/4, kq = (tid&3)*4
    const int kq = (tid & 3) * 4;
    int aB[2], aOy[2], aOx[2];
    bool aValid[2];
#pragma unroll
    for (int l = 0; l < 2; l++) {
        int m = l * 64 + (tid >> 2);
        int gm = bm0 + m;
        aValid[l] = (gm < M);
        int gmc = aValid[l] ? gm : 0;
        aB[l] = gmc / (HH * HH);
        int rr = gmc % (HH * HH);
        aOy[l] = rr / HH;
        aOx[l] = rr % HH;
    }
    // B-load: k = l*8 + tid/32, n = (tid&31)*4
    const int bK = tid >> 5;
    const int bN = (tid & 31) * 4;

    const int ty = tid >> 4;  // 0..15
    const int tx = tid & 15;  // 0..15

    float acc[8][8] = {};
    float4 aReg[2], bReg[2];

    auto loadTile = [&](int kt) {
        const int kk = kt * 16;
        const int tap = kk / CIN;  // 16 | CIN so one 3x3 tap per tile
        const int ky = tap / 3, kx = tap % 3;
        const int ciB = kk % CIN;
#pragma unroll
        for (int l = 0; l < 2; l++) {
            int iy = aOy[l] + ky - 1;
            int ix = aOx[l] + kx - 1;
            float4 v = make_float4(0.f, 0.f, 0.f, 0.f);
            if (aValid[l] && iy >= 0 && iy < HH && ix >= 0 && ix < HH)
                v = *(const float4*)&in[(((size_t)aB[l] * HH + iy) * HH + ix) * CIN + ciB + kq];
            aReg[l] = v;
            bReg[l] = *(const float4*)&w[(size_t)(kk + l * 8 + bK) * COUT + bn0 + bN];
        }
    };
    auto storeTile = [&](int buf) {
#pragma unroll
        for (int l = 0; l < 2; l++) {
            int m = l * 64 + (tid >> 2);
            As[buf][kq + 0][m] = aReg[l].x;
            As[buf][kq + 1][m] = aReg[l].y;
            As[buf][kq + 2][m] = aReg[l].z;
            As[buf][kq + 3][m] = aReg[l].w;
            *(float4*)&Bs[buf][l * 8 + bK][bN] = bReg[l];
        }
    };

    loadTile(0);
    storeTile(0);
    __syncthreads();

    for (int kt = 0; kt < NT; kt++) {
        const int buf = kt & 1;
        if (kt + 1 < NT) loadTile(kt + 1);
#pragma unroll
        for (int k = 0; k < 16; k++) {
            float4 a0 = *(float4*)&As[buf][k][ty * 4];
            float4 a1 = *(float4*)&As[buf][k][ty * 4 + 64];
            float4 b0 = *(float4*)&Bs[buf][k][tx * 4];
            float4 b1 = *(float4*)&Bs[buf][k][tx * 4 + 64];
            float av[8] = {a0.x, a0.y, a0.z, a0.w, a1.x, a1.y, a1.z, a1.w};
            float bv[8] = {b0.x, b0.y, b0.z, b0.w, b1.x, b1.y, b1.z, b1.w};
#pragma unroll
            for (int i = 0; i < 8; i++)
#pragma unroll
                for (int j = 0; j < 8; j++) acc[i][j] += av[i] * bv[j];
        }
        if (kt + 1 < NT) {
            storeTile(buf ^ 1);
            __syncthreads();
        }
    }

    // epilogue: scale/bias + leaky relu
    float4 g0 = *(const float4*)&gamma[bn0 + tx * 4];
    float4 g1 = *(const float4*)&gamma[bn0 + tx * 4 + 64];
    float4 e0 = *(const float4*)&beta[bn0 + tx * 4];
    float4 e1 = *(const float4*)&beta[bn0 + tx * 4 + 64];
    float gv[8] = {g0.x, g0.y, g0.z, g0.w, g1.x, g1.y, g1.z, g1.w};
    float ev[8] = {e0.x, e0.y, e0.z, e0.w, e1.x, e1.y, e1.z, e1.w};
#pragma unroll
    for (int i = 0; i < 8; i++) {
        int gm = bm0 + ty * 4 + (i & 3) + (i >> 2) * 64;
        if (gm < M) {
            float t[8];
#pragma unroll
            for (int j = 0; j < 8; j++) {
                float v = acc[i][j] * gv[j] + ev[j];
                t[j] = v > 0.f ? v : 0.1f * v;
            }
            *(float4*)&g_x[(size_t)gm * COUT + bn0 + tx * 4] =
                make_float4(t[0], t[1], t[2], t[3]);
            *(float4*)&g_x[(size_t)gm * COUT + bn0 + tx * 4 + 64] =
                make_float4(t[4], t[5], t[6], t[7]);
        }
    }
}

// ---------------- 1x1 conv (255 ch) + bias + decode ----------------
// Each block handles 8 pixels; thread t<255 computes pred channel t for all 8.
template <int HD, int HH>
__global__ __launch_bounds__(256) void pred_decode(const float* __restrict__ w1,
                                                   const float* __restrict__ bias,
                                                   int levelOff, float stride, int alevel) {
    constexpr int P = 8;
    __shared__ float xsh[P][HD];
    __shared__ float psh[P][256];
    const int tid = threadIdx.x;
    const int pix0 = blockIdx.x * P;

    for (int id = tid; id < P * (HD / 4); id += 256) {
        int p = id / (HD / 4);
        int r = id % (HD / 4);
        *(float4*)&xsh[p][r * 4] = *(const float4*)&g_x[(size_t)(pix0 + p) * HD + r * 4];
    }
    __syncthreads();

    if (tid < 255) {
        float acc[P];
        float bb = bias[tid];
#pragma unroll
        for (int p = 0; p < P; p++) acc[p] = bb;
#pragma unroll 4
        for (int k = 0; k < HD; k++) {
            float wv = w1[(size_t)k * 255 + tid];
#pragma unroll
            for (int p = 0; p < P; p++) acc[p] += xsh[p][k] * wv;
        }
#pragma unroll
        for (int p = 0; p < P; p++) psh[p][tid] = acc[p];
    }
    __syncthreads();

    // scores: 8 pixels * 3 anchors * 80 classes
    for (int wi = tid; wi < P * 240; wi += 256) {
        int p = wi / 240, r = wi % 240;
        int a = r / 80, c = r % 80;
        float so = sigmoidf_(psh[p][a * 85 + 4]);
        float sc = sigmoidf_(psh[p][a * 85 + 5 + c]);
        int pix = pix0 + p;
        int b = pix / (HH * HH);
        int rr = pix % (HH * HH);
        size_t aidx = (size_t)b * ATOT + levelOff + rr * 3 + a;
        g_scores[aidx * NCLS + c] = so * sc;
    }
    // boxes: 8 pixels * 3 anchors
    for (int wi = tid; wi < P * 3; wi += 256) {
        int p = wi / 3, a = wi % 3;
        int pix = pix0 + p;
        int b = pix / (HH * HH);
        int rr = pix % (HH * HH);
        int oy = rr / HH, ox = rr % HH;
        float tx = psh[p][a * 85 + 0];
        float ty = psh[p][a * 85 + 1];
        float tw = psh[p][a * 85 + 2];
        float th = psh[p][a * 85 + 3];
        float cx = ((sigmoidf_(tx) * 1.05f - 0.025f) + (float)ox) * stride;
        float cy = ((sigmoidf_(ty) * 1.05f - 0.025f) + (float)oy) * stride;
        float bw = expf(tw) * c_anchors[alevel][a][0];
        float bh = expf(th) * c_anchors[alevel][a][1];
        size_t aidx = (size_t)b * ATOT + levelOff + rr * 3 + a;
        float* bp = &g_boxes[aidx * 4];
        bp[0] = cx - 0.5f * bw;
        bp[1] = cy - 0.5f * bh;
        bp[2] = cx + 0.5f * bw;
        bp[3] = cy + 0.5f * bh;
    }
}

// ---------------- top-400 selection: 2-level radix histogram on float bits ----------------
__global__ void hist1_kernel() {
    __shared__ unsigned h[4096];
    for (int i = threadIdx.x; i < 4096; i += blockDim.x) h[i] = 0u;
    __syncthreads();
    int b = blockIdx.y;
    const float* sc = &g_scores[(size_t)b * NFLAT];
    int start = blockIdx.x * 4096;
    int end = min(start + 4096, NFLAT);
    for (int i = start + (int)threadIdx.x; i < end; i += blockDim.x) {
        float s = sc[i];
        unsigned bits = (s >= 0.05f) ? __float_as_uint(s) : 0u;
        atomicAdd(&h[bits >> 20], 1u);
    }
    __syncthreads();
    for (int i = threadIdx.x; i < 4096; i += blockDim.x)
        if (h[i]) atomicAdd(&g_hist1[b * 4096 + i], h[i]);
}

__global__ void scan1_kernel() {
    __shared__ unsigned s[1024];
    int b = blockIdx.x, tid = threadIdx.x;
    unsigned v[4], sum = 0;
#pragma unroll
    for (int j = 0; j < 4; j++) {
        v[j] = g_hist1[b * 4096 + 4095 - (tid * 4 + j)];
        sum += v[j];
    }
    s[tid] = sum;
    __syncthreads();
    for (int off = 1; off < 1024; off <<= 1) {
        unsigned t = (tid >= off) ? s[tid - off] : 0u;
        __syncthreads();
        s[tid] += t;
        __syncthreads();
    }
    unsigned excl = s[tid] - sum;
    unsigned cum = excl;
#pragma unroll
    for (int j = 0; j < 4; j++) {
        if (cum < PRE_NMS && cum + v[j] >= PRE_NMS) {
            g_b1[b] = 4095 - (tid * 4 + j);
            g_prefix1[b] = cum;
        }
        cum += v[j];
    }
}

__global__ void hist2_kernel() {
    __shared__ unsigned h[4096];
    for (int i = threadIdx.x; i < 4096; i += blockDim.x) h[i] = 0u;
    __syncthreads();
    int b = blockIdx.y;
    unsigned b1 = g_b1[b];
    const float* sc = &g_scores[(size_t)b * NFLAT];
    int start = blockIdx.x * 4096;
    int end = min(start + 4096, NFLAT);
    for (int i = start + (int)threadIdx.x; i < end; i += blockDim.x) {
        float s = sc[i];
        unsigned bits = (s >= 0.05f) ? __float_as_uint(s) : 0u;
        if ((bits >> 20) == b1) atomicAdd(&h[(bits >> 8) & 0xFFFu], 1u);
    }
    __syncthreads();
    for (int i = threadIdx.x; i < 4096; i += blockDim.x)
        if (h[i]) atomicAdd(&g_hist2[b * 4096 + i], h[i]);
}

__global__ void scan2_kernel() {
    __shared__ unsigned s[1024];
    int b = blockIdx.x, tid = threadIdx.x;
    unsigned target = PRE_NMS - g_prefix1[b];  // >= 1 by construction
    unsigned v[4], sum = 0;
#pragma unroll
    for (int j = 0; j < 4; j++) {
        v[j] = g_hist2[b * 4096 + 4095 - (tid * 4 + j)];
        sum += v[j];
    }
    s[tid] = sum;
    __syncthreads();
    for (int off = 1; off < 1024; off <<= 1) {
        unsigned t = (tid >= off) ? s[tid - off] : 0u;
        __syncthreads();
        s[tid] += t;
        __syncthreads();
    }
    unsigned excl = s[tid] - sum;
    unsigned cum = excl;
#pragma unroll
    for (int j = 0; j < 4; j++) {
        if (cum < target && cum + v[j] >= target) {
            g_pivot[b] = (g_b1[b] << 12) | (unsigned)(4095 - (tid * 4 + j));
        }
        cum += v[j];
    }
}

__global__ void compact_kernel() {
    int b = blockIdx.y;
    unsigned pivot = g_pivot[b];
    const float* sc = &g_scores[(size_t)b * NFLAT];
    int start = blockIdx.x * 4096;
    int end = min(start + 4096, NFLAT);
    for (int i = start + (int)threadIdx.x; i < end; i += blockDim.x) {
        float s = sc[i];
        unsigned bits = (s >= 0.05f) ? __float_as_uint(s) : 0u;
        if ((bits >> 8) >= pivot) {
            unsigned pos = atomicAdd(&g_cnt[b], 1u);
            if (pos < 8192)
                g_cand[b * 8192 + pos] =
                    ((unsigned long long)bits << 32) |
                    (unsigned long long)(0xFFFFFFFFu - (unsigned)i);
        }
    }
}

// ---------------- exact top-k sort + greedy NMS + final top-100 ----------------
__global__ __launch_bounds__(512) void nms_kernel(float* __restrict__ out) {
    constexpr int NC = 2048;
    __shared__ unsigned long long keys[NC];
    __shared__ float boSh[PRE_NMS][4];
    __shared__ float areaSh[PRE_NMS];
    __shared__ float scSh[PRE_NMS];
    __shared__ int keepSh[PRE_NMS];
    __shared__ int aiSh[PRE_NMS];
    __shared__ int ciSh[PRE_NMS];
    __shared__ unsigned long long key2[512];

    int b = blockIdx.x;
    int tid = threadIdx.x;
    int cnt = min((int)g_cnt[b], NC);
    for (int i = tid; i < NC; i += 512)
        keys[i] = (i < cnt) ? g_cand[b * 8192 + i] : 0ull;
    __syncthreads();

    // bitonic ascending sort over NC composite keys (score_bits, ~flat_idx)
    for (int k = 2; k <= NC; k <<= 1) {
        for (int j = k >> 1; j > 0; j >>= 1) {
            for (int i = tid; i < NC; i += 512) {
                int ixj = i ^ j;
                if (ixj > i) {
                    bool up = ((i & k) == 0);
                    unsigned long long a = keys[i], c = keys[ixj];
                    if (up ? (a > c) : (a < c)) { keys[i] = c; keys[ixj] = a; }
                }
            }
            __syncthreads();
        }
    }

    // extract top-400 (descending), build offset boxes exactly like reference
    if (tid < PRE_NMS) {
        unsigned long long key = keys[NC - 1 - tid];
        unsigned bits = (unsigned)(key >> 32);
        unsigned flat = 0xFFFFFFFFu - (unsigned)(key & 0xFFFFFFFFull);
        if (key == 0ull) { bits = 0u; flat = 0u; }
        float s = __uint_as_float(bits);
        int a = (int)(flat / NCLS);
        int c = (int)(flat % NCLS);
        const float* bp = &g_boxes[((size_t)b * ATOT + a) * 4];
        float off = (float)c * 1216.0f;  // c * 2*IMG_SIZE
        float x0 = bp[0] + off, y0 = bp[1] + off;
        float x1 = bp[2] + off, y1 = bp[3] + off;
        boSh[tid][0] = x0; boSh[tid][1] = y0; boSh[tid][2] = x1; boSh[tid][3] = y1;
        areaSh[tid] = (x1 - x0) * (y1 - y0);
        scSh[tid] = s;
        keepSh[tid] = 1;
        aiSh[tid] = a;
        ciSh[tid] = c;
    }
    __syncthreads();

    // greedy suppression, iteration order = score rank (matches fori_loop)
    for (int i = 0; i < PRE_NMS; i++) {
        bool act = (keepSh[i] != 0) && (scSh[i] > 0.f);
        if (act && tid > i && tid < PRE_NMS) {
            float lx = fmaxf(boSh[i][0], boSh[tid][0]);
            float ly = fmaxf(boSh[i][1], boSh[tid][1]);
            float rx = fminf(boSh[i][2], boSh[tid][2]);
            float ry = fminf(boSh[i][3], boSh[tid][3]);
            float w = fmaxf(rx - lx, 0.f), h = fmaxf(ry - ly, 0.f);
            float inter = w * h;
            float iou = inter / (areaSh[i] + areaSh[tid] - inter + 1e-7f);
            if (iou > 0.5f) keepSh[tid] = 0;
        }
        __syncthreads();
    }

    // final scores + stable top-100
    {
        unsigned long long key = 0ull;
        if (tid < PRE_NMS) {
            float fin = (keepSh[tid] && scSh[tid] > 0.f) ? scSh[tid] : 0.f;
            key = ((unsigned long long)__float_as_uint(fin) << 32) |
                  (unsigned long long)(0xFFFFFFFFu - (unsigned)tid);
        }
        key2[tid] = key;
    }
    __syncthreads();
    for (int k = 2; k <= 512; k <<= 1) {
        for (int j = k >> 1; j > 0; j >>= 1) {
            int i = tid;
            int ixj = i ^ j;
            if (ixj > i) {
                bool up = ((i & k) == 0);
                unsigned long long a = key2[i], c = key2[ixj];
                if (up ? (a > c) : (a < c)) { key2[i] = c; key2[ixj] = a; }
            }
            __syncthreads();
        }
    }

    if (tid < MAX_DET) {
        unsigned long long key = key2[511 - tid];
        unsigned sb = (unsigned)(key >> 32);
        int pos = (int)(0xFFFFFFFFu - (unsigned)(key & 0xFFFFFFFFull));
        int a = aiSh[pos], c = ciSh[pos];
        const float* bp = &g_boxes[((size_t)b * ATOT + a) * 4];
        int d = b * MAX_DET + tid;
        out[d * 4 + 0] = bp[0];
        out[d * 4 + 1] = bp[1];
        out[d * 4 + 2] = bp[2];
        out[d * 4 + 3] = bp[3];
        out[BATCH * MAX_DET * 4 + d] = __uint_as_float(sb);
        out[BATCH * MAX_DET * 4 + BATCH * MAX_DET + d] = (float)c;
    }
}

// ---------------- launcher ----------------
extern "C" void kernel_launch(void* const* d_in, const int* in_sizes, int n_in,
                              void* d_out, int out_size) {
    (void)out_size;
    const float *f0 = nullptr, *f1 = nullptr, *f2 = nullptr;
    const float *w3[3] = {}, *ga[3] = {}, *be[3] = {}, *w1[3] = {}, *b1[3] = {};
    int c256 = 0, c512 = 0, c1024 = 0, c255 = 0;
    for (int i = 0; i < n_in; i++) {
        const float* p = (const float*)d_in[i];
        switch (in_sizes[i]) {
            case 5914624: f0 = p; break;                 // 8*76*76*128
            case 2957312: f1 = p; break;                 // 8*38*38*256
            case 1478656: f2 = p; break;                 // 8*19*19*512
            case 294912:  w3[0] = p; break;              // 3*3*128*256
            case 1179648: w3[1] = p; break;              // 3*3*256*512
            case 4718592: w3[2] = p; break;              // 3*3*512*1024
            case 65280:   w1[0] = p; break;              // 256*255
            case 130560:  w1[1] = p; break;              // 512*255
            case 261120:  w1[2] = p; break;              // 1024*255
            case 256:  if (c256++ == 0) ga[0] = p; else be[0] = p; break;
            case 512:  if (c512++ == 0) ga[1] = p; else be[1] = p; break;
            case 1024: if (c1024++ == 0) ga[2] = p; else be[2] = p; break;
            case 255:  if (c255 < 3) b1[c255++] = p; break;
        }
    }
    float* out = (float*)d_out;

    zero_misc<<<128, 256>>>();

    conv3x3<128, 256, 76><<<dim3(361, 2), 256>>>(f0, w3[0], ga[0], be[0]);
    pred_decode<256, 76><<<5776, 256>>>(w1[0], b1[0], 0, 8.0f, 0);

    conv3x3<256, 512, 38><<<dim3(91, 4), 256>>>(f1, w3[1], ga[1], be[1]);
    pred_decode<512, 38><<<1444, 256>>>(w1[1], b1[1], 17328, 16.0f, 1);

    conv3x3<512, 1024, 19><<<dim3(23, 8), 256>>>(f2, w3[2], ga[2], be[2]);
    pred_decode<1024, 19><<<361, 256>>>(w1[2], b1[2], 21660, 32.0f, 2);

    hist1_kernel<<<dim3(445, 8), 256>>>();
    scan1_kernel<<<8, 1024>>>();
    hist2_kernel<<<dim3(445, 8), 256>>>();
    scan2_kernel<<<8, 1024>>>();
    compact_kernel<<<dim3(445, 8), 256>>>();
    nms_kernel<<<8, 512>>>(out);
}

// round 6
// speedup vs baseline: 1.0893x; 1.0893x over previous
#include <cuda_runtime.h>
#include <cstddef>

// ---------------- problem constants ----------------
#define BATCH 8
#define NCLS 80
#define ATOT 22743            // 76*76*3 + 38*38*3 + 19*19*3
#define NFLAT (ATOT * NCLS)   // 1,819,440 per batch
#define PRE_NMS 400
#define MAX_DET 100

typedef unsigned long long ull;

// ---------------- static scratch (no runtime allocs allowed) ----------------
__device__ float g_x[46208 * 256];                         // tower activations (max level 0), 47MB
__device__ float g_boxes[BATCH * ATOT * 4];                // decoded boxes
__device__ float g_scores[(size_t)BATCH * NFLAT];          // decoded scores, 58MB
__device__ unsigned g_hist1[BATCH * 4096];
__device__ unsigned g_hist2[BATCH * 4096];
__device__ unsigned g_b1[BATCH];
__device__ unsigned g_prefix1[BATCH];
__device__ unsigned g_pivot[BATCH];
__device__ unsigned g_cnt[BATCH];
__device__ unsigned long long g_cand[BATCH * 8192];

__constant__ float c_anchors[3][3][2] = {
    {{12.f, 16.f}, {19.f, 36.f}, {40.f, 28.f}},
    {{36.f, 75.f}, {76.f, 55.f}, {72.f, 146.f}},
    {{142.f, 110.f}, {192.f, 243.f}, {459.f, 401.f}}};

__device__ __forceinline__ float sigmoidf_(float x) { return 1.0f / (1.0f + expf(-x)); }

// ---- packed fp32x2 FMA helpers (Blackwell FFMA2: full-rate fp32 path) ----
__device__ __forceinline__ void ffma2(ull& d, ull a, ull b) {
    asm("fma.rn.f32x2 %0, %1, %2, %0;" : "+l"(d) : "l"(a), "l"(b));
}
__device__ __forceinline__ ull dup2(float x) {
    ull r;
    asm("mov.b64 %0, {%1, %1};" : "=l"(r) : "f"(x));
    return r;
}
__device__ __forceinline__ ull pack2(float lo, float hi) {
    ull r;
    asm("mov.b64 %0, {%1, %2};" : "=l"(r) : "f"(lo), "f"(hi));
    return r;
}
__device__ __forceinline__ void unpack2(float& lo, float& hi, ull v) {
    asm("mov.b64 {%0, %1}, %2;" : "=f"(lo), "=f"(hi) : "l"(v));
}

// ---------------- init ----------------
__global__ void zero_misc() {
    int i = blockIdx.x * blockDim.x + threadIdx.x;
    if (i < BATCH * 4096) { g_hist1[i] = 0u; g_hist2[i] = 0u; }
    if (i < BATCH) {
        g_cnt[i] = 0u;
        g_b1[i] = 0u;
        g_prefix1[i] = 0u;
        g_pivot[i] = 0u;
    }
}

// ---------------- fused conv3x3 + scale/bias + leaky-relu ----------------
// Implicit-GEMM: M = BATCH*H*H pixels, N = COUT, K = 9*CIN.
// BM=128, BN=64, BK=16, 256 threads, 8x4 microtile with packed f32x2 FMA.
// Scalar FFMA is half-rate on sm_100 (rt_SMSP=2): R2/R4/R5 all capped ~50%.
// fma.rn.f32x2 restores the full 128 FMA/cyc/SM rate. acc = 16 b64 = 32 regs
// -> ~80 regs total -> 3 CTAs/SM for latency hiding.
template <int CIN, int COUT, int HH>
__global__ __launch_bounds__(256, 2) void conv3x3(const float* __restrict__ in,
                                                  const float* __restrict__ w,
                                                  const float* __restrict__ gamma,
                                                  const float* __restrict__ beta) {
    constexpr int M = BATCH * HH * HH;
    constexpr int KTOT = 9 * CIN;
    constexpr int NT = KTOT / 16;
    __shared__ float As[2][16][132];  // [buf][k][m]
    __shared__ float Bs[2][16][68];   // [buf][k][n]

    const int tid = threadIdx.x;
    const int bm0 = blockIdx.x * 128;
    const int bn0 = blockIdx.y * 64;

    // A-load: 2 float4/thread; row m = l*64 + tid/4, k-quad = (tid&3)*4
    const int kq = (tid & 3) * 4;
    int aB[2], aOy[2], aOx[2];
    bool aValid[2];
#pragma unroll
    for (int l = 0; l < 2; l++) {
        int m = l * 64 + (tid >> 2);
        int gm = bm0 + m;
        aValid[l] = (gm < M);
        int gmc = aValid[l] ? gm : 0;
        aB[l] = gmc / (HH * HH);
        int rr = gmc % (HH * HH);
        aOy[l] = rr / HH;
        aOx[l] = rr % HH;
    }
    // B-load: 1 float4/thread; k = tid/16, n = (tid&15)*4
    const int bK = tid >> 4;
    const int bN = (tid & 15) * 4;

    const int ty = tid >> 4;  // 0..15 -> rows ty*4..+3 and +64
    const int tx = tid & 15;  // 0..15 -> cols tx*4..+3

    ull acc[8][2];
#pragma unroll
    for (int i = 0; i < 8; i++) { acc[i][0] = 0ull; acc[i][1] = 0ull; }
    float4 aReg[2], bReg;

    auto loadTile = [&](int kt) {
        const int kk = kt * 16;
        const int tap = kk / CIN;  // 16 | CIN so one 3x3 tap per tile
        const int ky = tap / 3, kx = tap % 3;
        const int ciB = kk % CIN;
#pragma unroll
        for (int l = 0; l < 2; l++) {
            int iy = aOy[l] + ky - 1;
            int ix = aOx[l] + kx - 1;
            float4 v = make_float4(0.f, 0.f, 0.f, 0.f);
            if (aValid[l] && iy >= 0 && iy < HH && ix >= 0 && ix < HH)
                v = *(const float4*)&in[(((size_t)aB[l] * HH + iy) * HH + ix) * CIN + ciB + kq];
            aReg[l] = v;
        }
        bReg = *(const float4*)&w[(size_t)(kk + bK) * COUT + bn0 + bN];
    };
    auto storeTile = [&](int buf) {
#pragma unroll
        for (int l = 0; l < 2; l++) {
            int m = l * 64 + (tid >> 2);
            As[buf][kq + 0][m] = aReg[l].x;
            As[buf][kq + 1][m] = aReg[l].y;
            As[buf][kq + 2][m] = aReg[l].z;
            As[buf][kq + 3][m] = aReg[l].w;
        }
        *(float4*)&Bs[buf][bK][bN] = bReg;
    };

    loadTile(0);
    storeTile(0);
    __syncthreads();

    for (int kt = 0; kt < NT; kt++) {
        const int buf = kt & 1;
        if (kt + 1 < NT) loadTile(kt + 1);
#pragma unroll
        for (int k = 0; k < 16; k++) {
            float4 a0 = *(float4*)&As[buf][k][ty * 4];
            float4 a1 = *(float4*)&As[buf][k][ty * 4 + 64];
            float4 b0 = *(float4*)&Bs[buf][k][tx * 4];
            ull bp0 = pack2(b0.x, b0.y);
            ull bp1 = pack2(b0.z, b0.w);
            float av[8] = {a0.x, a0.y, a0.z, a0.w, a1.x, a1.y, a1.z, a1.w};
#pragma unroll
            for (int i = 0; i < 8; i++) {
                ull ad = dup2(av[i]);
                ffma2(acc[i][0], ad, bp0);
                ffma2(acc[i][1], ad, bp1);
            }
        }
        if (kt + 1 < NT) {
            storeTile(buf ^ 1);
            __syncthreads();
        }
    }

    // epilogue: scale/bias + leaky relu
    float4 g0 = *(const float4*)&gamma[bn0 + tx * 4];
    float4 e0 = *(const float4*)&beta[bn0 + tx * 4];
    float gv[4] = {g0.x, g0.y, g0.z, g0.w};
    float ev[4] = {e0.x, e0.y, e0.z, e0.w};
#pragma unroll
    for (int i = 0; i < 8; i++) {
        int gm = bm0 + ty * 4 + (i & 3) + (i >> 2) * 64;
        if (gm < M) {
            float c[4];
            unpack2(c[0], c[1], acc[i][0]);
            unpack2(c[2], c[3], acc[i][1]);
            float t[4];
#pragma unroll
            for (int j = 0; j < 4; j++) {
                float v = c[j] * gv[j] + ev[j];
                t[j] = v > 0.f ? v : 0.1f * v;
            }
            *(float4*)&g_x[(size_t)gm * COUT + bn0 + tx * 4] =
                make_float4(t[0], t[1], t[2], t[3]);
        }
    }
}

// ---------------- 1x1 conv (255 ch) + bias + decode ----------------
// Each block handles 8 pixels; thread t<255 computes pred channel t for all 8.
template <int HD, int HH>
__global__ __launch_bounds__(256) void pred_decode(const float* __restrict__ w1,
                                                   const float* __restrict__ bias,
                                                   int levelOff, float stride, int alevel) {
    constexpr int P = 8;
    __shared__ float xsh[P][HD];
    __shared__ float psh[P][256];
    const int tid = threadIdx.x;
    const int pix0 = blockIdx.x * P;

    for (int id = tid; id < P * (HD / 4); id += 256) {
        int p = id / (HD / 4);
        int r = id % (HD / 4);
        *(float4*)&xsh[p][r * 4] = *(const float4*)&g_x[(size_t)(pix0 + p) * HD + r * 4];
    }
    __syncthreads();

    if (tid < 255) {
        // packed pairs over pixels: acc2[q] = pixels (2q, 2q+1)
        ull acc2[P / 2];
        float bb = bias[tid];
        ull bb2 = pack2(bb, bb);
#pragma unroll
        for (int q = 0; q < P / 2; q++) acc2[q] = bb2;
#pragma unroll 4
        for (int k = 0; k < HD; k++) {
            ull wv = dup2(w1[(size_t)k * 255 + tid]);
#pragma unroll
            for (int q = 0; q < P / 2; q++) {
                ull xp = pack2(xsh[2 * q][k], xsh[2 * q + 1][k]);
                ffma2(acc2[q], wv, xp);
            }
        }
#pragma unroll
        for (int q = 0; q < P / 2; q++) {
            float lo, hi;
            unpack2(lo, hi, acc2[q]);
            psh[2 * q][tid] = lo;
            psh[2 * q + 1][tid] = hi;
        }
    }
    __syncthreads();

    // scores: 8 pixels * 3 anchors * 80 classes
    for (int wi = tid; wi < P * 240; wi += 256) {
        int p = wi / 240, r = wi % 240;
        int a = r / 80, c = r % 80;
        float so = sigmoidf_(psh[p][a * 85 + 4]);
        float sc = sigmoidf_(psh[p][a * 85 + 5 + c]);
        int pix = pix0 + p;
        int b = pix / (HH * HH);
        int rr = pix % (HH * HH);
        size_t aidx = (size_t)b * ATOT + levelOff + rr * 3 + a;
        g_scores[aidx * NCLS + c] = so * sc;
    }
    // boxes: 8 pixels * 3 anchors
    for (int wi = tid; wi < P * 3; wi += 256) {
        int p = wi / 3, a = wi % 3;
        int pix = pix0 + p;
        int b = pix / (HH * HH);
        int rr = pix % (HH * HH);
        int oy = rr / HH, ox = rr % HH;
        float tx = psh[p][a * 85 + 0];
        float ty = psh[p][a * 85 + 1];
        float tw = psh[p][a * 85 + 2];
        float th = psh[p][a * 85 + 3];
        float cx = ((sigmoidf_(tx) * 1.05f - 0.025f) + (float)ox) * stride;
        float cy = ((sigmoidf_(ty) * 1.05f - 0.025f) + (float)oy) * stride;
        float bw = expf(tw) * c_anchors[alevel][a][0];
        float bh = expf(th) * c_anchors[alevel][a][1];
        size_t aidx = (size_t)b * ATOT + levelOff + rr * 3 + a;
        float* bp = &g_boxes[aidx * 4];
        bp[0] = cx - 0.5f * bw;
        bp[1] = cy - 0.5f * bh;
        bp[2] = cx + 0.5f * bw;
        bp[3] = cy + 0.5f * bh;
    }
}

// ---------------- top-400 selection: 2-level radix histogram on float bits ----------------
__global__ void hist1_kernel() {
    __shared__ unsigned h[4096];
    for (int i = threadIdx.x; i < 4096; i += blockDim.x) h[i] = 0u;
    __syncthreads();
    int b = blockIdx.y;
    const float* sc = &g_scores[(size_t)b * NFLAT];
    int start = blockIdx.x * 4096;
    int end = min(start + 4096, NFLAT);
    for (int i = start + (int)threadIdx.x; i < end; i += blockDim.x) {
        float s = sc[i];
        unsigned bits = (s >= 0.05f) ? __float_as_uint(s) : 0u;
        atomicAdd(&h[bits >> 20], 1u);
    }
    __syncthreads();
    for (int i = threadIdx.x; i < 4096; i += blockDim.x)
        if (h[i]) atomicAdd(&g_hist1[b * 4096 + i], h[i]);
}

__global__ void scan1_kernel() {
    __shared__ unsigned s[1024];
    int b = blockIdx.x, tid = threadIdx.x;
    unsigned v[4], sum = 0;
#pragma unroll
    for (int j = 0; j < 4; j++) {
        v[j] = g_hist1[b * 4096 + 4095 - (tid * 4 + j)];
        sum += v[j];
    }
    s[tid] = sum;
    __syncthreads();
    for (int off = 1; off < 1024; off <<= 1) {
        unsigned t = (tid >= off) ? s[tid - off] : 0u;
        __syncthreads();
        s[tid] += t;
        __syncthreads();
    }
    unsigned excl = s[tid] - sum;
    unsigned cum = excl;
#pragma unroll
    for (int j = 0; j < 4; j++) {
        if (cum < PRE_NMS && cum + v[j] >= PRE_NMS) {
            g_b1[b] = 4095 - (tid * 4 + j);
            g_prefix1[b] = cum;
        }
        cum += v[j];
    }
}

__global__ void hist2_kernel() {
    __shared__ unsigned h[4096];
    for (int i = threadIdx.x; i < 4096; i += blockDim.x) h[i] = 0u;
    __syncthreads();
    int b = blockIdx.y;
    unsigned b1 = g_b1[b];
    const float* sc = &g_scores[(size_t)b * NFLAT];
    int start = blockIdx.x * 4096;
    int end = min(start + 4096, NFLAT);
    for (int i = start + (int)threadIdx.x; i < end; i += blockDim.x) {
        float s = sc[i];
        unsigned bits = (s >= 0.05f) ? __float_as_uint(s) : 0u;
        if ((bits >> 20) == b1) atomicAdd(&h[(bits >> 8) & 0xFFFu], 1u);
    }
    __syncthreads();
    for (int i = threadIdx.x; i < 4096; i += blockDim.x)
        if (h[i]) atomicAdd(&g_hist2[b * 4096 + i], h[i]);
}

__global__ void scan2_kernel() {
    __shared__ unsigned s[1024];
    int b = blockIdx.x, tid = threadIdx.x;
    unsigned target = PRE_NMS - g_prefix1[b];  // >= 1 by construction
    unsigned v[4], sum = 0;
#pragma unroll
    for (int j = 0; j < 4; j++) {
        v[j] = g_hist2[b * 4096 + 4095 - (tid * 4 + j)];
        sum += v[j];
    }
    s[tid] = sum;
    __syncthreads();
    for (int off = 1; off < 1024; off <<= 1) {
        unsigned t = (tid >= off) ? s[tid - off] : 0u;
        __syncthreads();
        s[tid] += t;
        __syncthreads();
    }
    unsigned excl = s[tid] - sum;
    unsigned cum = excl;
#pragma unroll
    for (int j = 0; j < 4; j++) {
        if (cum < target && cum + v[j] >= target) {
            g_pivot[b] = (g_b1[b] << 12) | (unsigned)(4095 - (tid * 4 + j));
        }
        cum += v[j];
    }
}

__global__ void compact_kernel() {
    int b = blockIdx.y;
    unsigned pivot = g_pivot[b];
    const float* sc = &g_scores[(size_t)b * NFLAT];
    int start = blockIdx.x * 4096;
    int end = min(start + 4096, NFLAT);
    for (int i = start + (int)threadIdx.x; i < end; i += blockDim.x) {
        float s = sc[i];
        unsigned bits = (s >= 0.05f) ? __float_as_uint(s) : 0u;
        if ((bits >> 8) >= pivot) {
            unsigned pos = atomicAdd(&g_cnt[b], 1u);
            if (pos < 8192)
                g_cand[b * 8192 + pos] =
                    ((unsigned long long)bits << 32) |
                    (unsigned long long)(0xFFFFFFFFu - (unsigned)i);
        }
    }
}

// ---------------- exact top-k sort + greedy NMS + final top-100 ----------------
__global__ __launch_bounds__(512) void nms_kernel(float* __restrict__ out) {
    constexpr int NC = 2048;
    __shared__ unsigned long long keys[NC];
    __shared__ float boSh[PRE_NMS][4];
    __shared__ float areaSh[PRE_NMS];
    __shared__ float scSh[PRE_NMS];
    __shared__ int keepSh[PRE_NMS];
    __shared__ int aiSh[PRE_NMS];
    __shared__ int ciSh[PRE_NMS];
    __shared__ unsigned long long key2[512];

    int b = blockIdx.x;
    int tid = threadIdx.x;
    int cnt = min((int)g_cnt[b], NC);
    for (int i = tid; i < NC; i += 512)
        keys[i] = (i < cnt) ? g_cand[b * 8192 + i] : 0ull;
    __syncthreads();

    // bitonic ascending sort over NC composite keys (score_bits, ~flat_idx)
    for (int k = 2; k <= NC; k <<= 1) {
        for (int j = k >> 1; j > 0; j >>= 1) {
            for (int i = tid; i < NC; i += 512) {
                int ixj = i ^ j;
                if (ixj > i) {
                    bool up = ((i & k) == 0);
                    unsigned long long a = keys[i], c = keys[ixj];
                    if (up ? (a > c) : (a < c)) { keys[i] = c; keys[ixj] = a; }
                }
            }
            __syncthreads();
        }
    }

    // extract top-400 (descending), build offset boxes exactly like reference
    if (tid < PRE_NMS) {
        unsigned long long key = keys[NC - 1 - tid];
        unsigned bits = (unsigned)(key >> 32);
        unsigned flat = 0xFFFFFFFFu - (unsigned)(key & 0xFFFFFFFFull);
        if (key == 0ull) { bits = 0u; flat = 0u; }
        float s = __uint_as_float(bits);
        int a = (int)(flat / NCLS);
        int c = (int)(flat % NCLS);
        const float* bp = &g_boxes[((size_t)b * ATOT + a) * 4];
        float off = (float)c * 1216.0f;  // c * 2*IMG_SIZE
        float x0 = bp[0] + off, y0 = bp[1] + off;
        float x1 = bp[2] + off, y1 = bp[3] + off;
        boSh[tid][0] = x0; boSh[tid][1] = y0; boSh[tid][2] = x1; boSh[tid][3] = y1;
        areaSh[tid] = (x1 - x0) * (y1 - y0);
        scSh[tid] = s;
        keepSh[tid] = 1;
        aiSh[tid] = a;
        ciSh[tid] = c;
    }
    __syncthreads();

    // greedy suppression, iteration order = score rank (matches fori_loop)
    for (int i = 0; i < PRE_NMS; i++) {
        bool act = (keepSh[i] != 0) && (scSh[i] > 0.f);
        if (act && tid > i && tid < PRE_NMS) {
            float lx = fmaxf(boSh[i][0], boSh[tid][0]);
            float ly = fmaxf(boSh[i][1], boSh[tid][1]);
            float rx = fminf(boSh[i][2], boSh[tid][2]);
            float ry = fminf(boSh[i][3], boSh[tid][3]);
            float w = fmaxf(rx - lx, 0.f), h = fmaxf(ry - ly, 0.f);
            float inter = w * h;
            float iou = inter / (areaSh[i] + areaSh[tid] - inter + 1e-7f);
            if (iou > 0.5f) keepSh[tid] = 0;
        }
        __syncthreads();
    }

    // final scores + stable top-100
    {
        unsigned long long key = 0ull;
        if (tid < PRE_NMS) {
            float fin = (keepSh[tid] && scSh[tid] > 0.f) ? scSh[tid] : 0.f;
            key = ((unsigned long long)__float_as_uint(fin) << 32) |
                  (unsigned long long)(0xFFFFFFFFu - (unsigned)tid);
        }
        key2[tid] = key;
    }
    __syncthreads();
    for (int k = 2; k <= 512; k <<= 1) {
        for (int j = k >> 1; j > 0; j >>= 1) {
            int i = tid;
            int ixj = i ^ j;
            if (ixj > i) {
                bool up = ((i & k) == 0);
                unsigned long long a = key2[i], c = key2[ixj];
                if (up ? (a > c) : (a < c)) { key2[i] = c; key2[ixj] = a; }
            }
            __syncthreads();
        }
    }

    if (tid < MAX_DET) {
        unsigned long long key = key2[511 - tid];
        unsigned sb = (unsigned)(key >> 32);
        int pos = (int)(0xFFFFFFFFu - (unsigned)(key & 0xFFFFFFFFull));
        int a = aiSh[pos], c = ciSh[pos];
        const float* bp = &g_boxes[((size_t)b * ATOT + a) * 4];
        int d = b * MAX_DET + tid;
        out[d * 4 + 0] = bp[0];
        out[d * 4 + 1] = bp[1];
        out[d * 4 + 2] = bp[2];
        out[d * 4 + 3] = bp[3];
        out[BATCH * MAX_DET * 4 + d] = __uint_as_float(sb);
        out[BATCH * MAX_DET * 4 + BATCH * MAX_DET + d] = (float)c;
    }
}

// ---------------- launcher ----------------
extern "C" void kernel_launch(void* const* d_in, const int* in_sizes, int n_in,
                              void* d_out, int out_size) {
    (void)out_size;
    const float *f0 = nullptr, *f1 = nullptr, *f2 = nullptr;
    const float *w3[3] = {}, *ga[3] = {}, *be[3] = {}, *w1[3] = {}, *b1[3] = {};
    int c256 = 0, c512 = 0, c1024 = 0, c255 = 0;
    for (int i = 0; i < n_in; i++) {
        const float* p = (const float*)d_in[i];
        switch (in_sizes[i]) {
            case 5914624: f0 = p; break;                 // 8*76*76*128
            case 2957312: f1 = p; break;                 // 8*38*38*256
            case 1478656: f2 = p; break;                 // 8*19*19*512
            case 294912:  w3[0] = p; break;              // 3*3*128*256
            case 1179648: w3[1] = p; break;              // 3*3*256*512
            case 4718592: w3[2] = p; break;              // 3*3*512*1024
            case 65280:   w1[0] = p; break;              // 256*255
            case 130560:  w1[1] = p; break;              // 512*255
            case 261120:  w1[2] = p; break;              // 1024*255
            case 256:  if (c256++ == 0) ga[0] = p; else be[0] = p; break;
            case 512:  if (c512++ == 0) ga[1] = p; else be[1] = p; break;
            case 1024: if (c1024++ == 0) ga[2] = p; else be[2] = p; break;
            case 255:  if (c255 < 3) b1[c255++] = p; break;
        }
    }
    float* out = (float*)d_out;

    zero_misc<<<128, 256>>>();

    conv3x3<128, 256, 76><<<dim3(361, 4), 256>>>(f0, w3[0], ga[0], be[0]);
    pred_decode<256, 76><<<5776, 256>>>(w1[0], b1[0], 0, 8.0f, 0);

    conv3x3<256, 512, 38><<<dim3(91, 8), 256>>>(f1, w3[1], ga[1], be[1]);
    pred_decode<512, 38><<<1444, 256>>>(w1[1], b1[1], 17328, 16.0f, 1);

    conv3x3<512, 1024, 19><<<dim3(23, 16), 256>>>(f2, w3[2], ga[2], be[2]);
    pred_decode<1024, 19><<<361, 256>>>(w1[2], b1[2], 21660, 32.0f, 2);

    hist1_kernel<<<dim3(445, 8), 256>>>();
    scan1_kernel<<<8, 1024>>>();
    hist2_kernel<<<dim3(445, 8), 256>>>();
    scan2_kernel<<<8, 1024>>>();
    compact_kernel<<<dim3(445, 8), 256>>>();
    nms_kernel<<<8, 512>>>(out);
}

// round 12
// speedup vs baseline: 1.3772x; 1.2643x over previous
#include <cuda_runtime.h>
#include <cstddef>

// ---------------- problem constants ----------------
#define BATCH 8
#define NCLS 80
#define ATOT 22743            // 76*76*3 + 38*38*3 + 19*19*3
#define NFLAT (ATOT * NCLS)   // 1,819,440 per batch
#define PRE_NMS 400
#define MAX_DET 100

// ---------------- static scratch (no runtime allocs allowed) ----------------
// Disjoint activation regions so all three conv levels can run concurrently.
#define XOFF0 0
#define XOFF1 11829248                      // 46208*256
#define XOFF2 (11829248 + 5914624)          // + 11552*512
__device__ float g_x[11829248 + 5914624 + 2957312];  // + 2888*1024  (83MB)
__device__ float g_boxes[BATCH * ATOT * 4];
__device__ float g_scores[(size_t)BATCH * NFLAT];
__device__ unsigned g_hist1[BATCH * 4096];
__device__ unsigned g_hist2[BATCH * 4096];
__device__ unsigned g_b1[BATCH];
__device__ unsigned g_prefix1[BATCH];
__device__ unsigned g_pivot[BATCH];
__device__ unsigned g_cnt[BATCH];
__device__ unsigned long long g_cand[BATCH * 8192];

__constant__ float c_anchors[3][3][2] = {
    {{12.f, 16.f}, {19.f, 36.f}, {40.f, 28.f}},
    {{36.f, 75.f}, {76.f, 55.f}, {72.f, 146.f}},
    {{142.f, 110.f}, {192.f, 243.f}, {459.f, 401.f}}};

__device__ __forceinline__ float sigmoidf_(float x) { return 1.0f / (1.0f + expf(-x)); }

// ---------------- init ----------------
__global__ void zero_misc() {
    int i = blockIdx.x * blockDim.x + threadIdx.x;
    if (i < BATCH * 4096) { g_hist1[i] = 0u; g_hist2[i] = 0u; }
    if (i < BATCH) {
        g_cnt[i] = 0u;
        g_b1[i] = 0u;
        g_prefix1[i] = 0u;
        g_pivot[i] = 0u;
    }
}

// ---------------- conv3x3 body: VERBATIM R4 (proven, 2958.7us baseline) ----------------
// Implicit-GEMM: M = BATCH*H*H pixels, N = COUT, K = 9*CIN.
// BM=128, BN=128, BK=16, 256 threads, 8x8 microtile, double-buffered smem.
template <int CIN, int COUT, int HH>
__device__ __forceinline__ void conv_body(
    int bm0, int bn0,
    const float* __restrict__ in, const float* __restrict__ w,
    const float* __restrict__ gamma, const float* __restrict__ beta,
    float* __restrict__ out,
    float (*As)[16][132], float (*Bs)[16][132]) {
    constexpr int M = BATCH * HH * HH;
    constexpr int KTOT = 9 * CIN;
    constexpr int NT = KTOT / 16;

    const int tid = threadIdx.x;

    // A-load per-thread coords: 2 float4 loads, row m = l*64 + tid/4, kq = (tid&3)*4
    const int kq = (tid & 3) * 4;
    int aB[2], aOy[2], aOx[2];
    bool aValid[2];
#pragma unroll
    for (int l = 0; l < 2; l++) {
        int m = l * 64 + (tid >> 2);
        int gm = bm0 + m;
        aValid[l] = (gm < M);
        int gmc = aValid[l] ? gm : 0;
        aB[l] = gmc / (HH * HH);
        int rr = gmc % (HH * HH);
        aOy[l] = rr / HH;
        aOx[l] = rr % HH;
    }
    // B-load: k = l*8 + tid/32, n = (tid&31)*4
    const int bK = tid >> 5;
    const int bN = (tid & 31) * 4;

    const int ty = tid >> 4;  // 0..15
    const int tx = tid & 15;  // 0..15

    float acc[8][8] = {};
    float4 aReg[2], bReg[2];

    auto loadTile = [&](int kt) {
        const int kk = kt * 16;
        const int tap = kk / CIN;  // 16 | CIN so one 3x3 tap per tile
        const int ky = tap / 3, kx = tap % 3;
        const int ciB = kk % CIN;
#pragma unroll
        for (int l = 0; l < 2; l++) {
            int iy = aOy[l] + ky - 1;
            int ix = aOx[l] + kx - 1;
            float4 v = make_float4(0.f, 0.f, 0.f, 0.f);
            if (aValid[l] && iy >= 0 && iy < HH && ix >= 0 && ix < HH)
                v = *(const float4*)&in[(((size_t)aB[l] * HH + iy) * HH + ix) * CIN + ciB + kq];
            aReg[l] = v;
            bReg[l] = *(const float4*)&w[(size_t)(kk + l * 8 + bK) * COUT + bn0 + bN];
        }
    };
    auto storeTile = [&](int buf) {
#pragma unroll
        for (int l = 0; l < 2; l++) {
            int m = l * 64 + (tid >> 2);
            As[buf][kq + 0][m] = aReg[l].x;
            As[buf][kq + 1][m] = aReg[l].y;
            As[buf][kq + 2][m] = aReg[l].z;
            As[buf][kq + 3][m] = aReg[l].w;
            *(float4*)&Bs[buf][l * 8 + bK][bN] = bReg[l];
        }
    };

    loadTile(0);
    storeTile(0);
    __syncthreads();

    for (int kt = 0; kt < NT; kt++) {
        const int buf = kt & 1;
        if (kt + 1 < NT) loadTile(kt + 1);
#pragma unroll
        for (int k = 0; k < 16; k++) {
            float4 a0 = *(float4*)&As[buf][k][ty * 4];
            float4 a1 = *(float4*)&As[buf][k][ty * 4 + 64];
            float4 b0 = *(float4*)&Bs[buf][k][tx * 4];
            float4 b1 = *(float4*)&Bs[buf][k][tx * 4 + 64];
            float av[8] = {a0.x, a0.y, a0.z, a0.w, a1.x, a1.y, a1.z, a1.w};
            float bv[8] = {b0.x, b0.y, b0.z, b0.w, b1.x, b1.y, b1.z, b1.w};
#pragma unroll
            for (int i = 0; i < 8; i++)
#pragma unroll
                for (int j = 0; j < 8; j++) acc[i][j] += av[i] * bv[j];
        }
        if (kt + 1 < NT) {
            storeTile(buf ^ 1);
            __syncthreads();
        }
    }

    // epilogue: scale/bias + leaky relu
    float4 g0 = *(const float4*)&gamma[bn0 + tx * 4];
    float4 g1 = *(const float4*)&gamma[bn0 + tx * 4 + 64];
    float4 e0 = *(const float4*)&beta[bn0 + tx * 4];
    float4 e1 = *(const float4*)&beta[bn0 + tx * 4 + 64];
    float gv[8] = {g0.x, g0.y, g0.z, g0.w, g1.x, g1.y, g1.z, g1.w};
    float ev[8] = {e0.x, e0.y, e0.z, e0.w, e1.x, e1.y, e1.z, e1.w};
#pragma unroll
    for (int i = 0; i < 8; i++) {
        int gm = bm0 + ty * 4 + (i & 3) + (i >> 2) * 64;
        if (gm < M) {
            float t[8];
#pragma unroll
            for (int j = 0; j < 8; j++) {
                float v = acc[i][j] * gv[j] + ev[j];
                t[j] = v > 0.f ? v : 0.1f * v;
            }
            *(float4*)&out[(size_t)gm * COUT + bn0 + tx * 4] =
                make_float4(t[0], t[1], t[2], t[3]);
            *(float4*)&out[(size_t)gm * COUT + bn0 + tx * 4 + 64] =
                make_float4(t[4], t[5], t[6], t[7]);
        }
    }
}

// Fused conv: one launch packs all three levels' CTAs (heavy L2 blocks first so
// long CTAs start in wave 1; short L0 CTAs backfill the tails).
// Grid layout: [L2: 23x8 = 184][L1: 91x4 = 364][L0: 361x2 = 722] = 1270 blocks.
__global__ __launch_bounds__(256, 2) void conv_all(
    const float* __restrict__ f0, const float* __restrict__ f1, const float* __restrict__ f2,
    const float* __restrict__ w30, const float* __restrict__ w31, const float* __restrict__ w32,
    const float* __restrict__ ga0, const float* __restrict__ ga1, const float* __restrict__ ga2,
    const float* __restrict__ be0, const float* __restrict__ be1, const float* __restrict__ be2) {
    __shared__ float As[2][16][132];
    __shared__ float Bs[2][16][132];
    int b = blockIdx.x;
    if (b < 184) {
        conv_body<512, 1024, 19>((b % 23) * 128, (b / 23) * 128, f2, w32, ga2, be2,
                                 g_x + XOFF2, As, Bs);
    } else if (b < 184 + 364) {
        int r = b - 184;
        conv_body<256, 512, 38>((r % 91) * 128, (r / 91) * 128, f1, w31, ga1, be1,
                                g_x + XOFF1, As, Bs);
    } else {
        int r = b - 548;
        conv_body<128, 256, 76>((r % 361) * 128, (r / 361) * 128, f0, w30, ga0, be0,
                                g_x + XOFF0, As, Bs);
    }
}

// ---------------- 1x1 conv (255 ch) + bias + decode: VERBATIM R4 body ----------------
template <int HD, int HH>
__device__ __forceinline__ void pred_body(
    int pix0, const float* __restrict__ xin,
    const float* __restrict__ w1, const float* __restrict__ bias,
    int levelOff, float stride, int alevel,
    float* xsh /* [P][HD] */, float* psh /* [P][256] */) {
    constexpr int P = 8;
    const int tid = threadIdx.x;

    for (int id = tid; id < P * (HD / 4); id += 256) {
        int p = id / (HD / 4);
        int r = id % (HD / 4);
        *(float4*)&xsh[p * HD + r * 4] = *(const float4*)&xin[(size_t)(pix0 + p) * HD + r * 4];
    }
    __syncthreads();

    if (tid < 255) {
        float acc[P];
        float bb = bias[tid];
#pragma unroll
        for (int p = 0; p < P; p++) acc[p] = bb;
#pragma unroll 4
        for (int k = 0; k < HD; k++) {
            float wv = w1[(size_t)k * 255 + tid];
#pragma unroll
            for (int p = 0; p < P; p++) acc[p] += xsh[p * HD + k] * wv;
        }
#pragma unroll
        for (int p = 0; p < P; p++) psh[p * 256 + tid] = acc[p];
    }
    __syncthreads();

    // scores: 8 pixels * 3 anchors * 80 classes
    for (int wi = tid; wi < P * 240; wi += 256) {
        int p = wi / 240, r = wi % 240;
        int a = r / 80, c = r % 80;
        float so = sigmoidf_(psh[p * 256 + a * 85 + 4]);
        float sc = sigmoidf_(psh[p * 256 + a * 85 + 5 + c]);
        int pix = pix0 + p;
        int b = pix / (HH * HH);
        int rr = pix % (HH * HH);
        size_t aidx = (size_t)b * ATOT + levelOff + rr * 3 + a;
        g_scores[aidx * NCLS + c] = so * sc;
    }
    // boxes: 8 pixels * 3 anchors
    for (int wi = tid; wi < P * 3; wi += 256) {
        int p = wi / 3, a = wi % 3;
        int pix = pix0 + p;
        int b = pix / (HH * HH);
        int rr = pix % (HH * HH);
        int oy = rr / HH, ox = rr % HH;
        float tx = psh[p * 256 + a * 85 + 0];
        float ty = psh[p * 256 + a * 85 + 1];
        float tw = psh[p * 256 + a * 85 + 2];
        float th = psh[p * 256 + a * 85 + 3];
        float cx = ((sigmoidf_(tx) * 1.05f - 0.025f) + (float)ox) * stride;
        float cy = ((sigmoidf_(ty) * 1.05f - 0.025f) + (float)oy) * stride;
        float bw = expf(tw) * c_anchors[alevel][a][0];
        float bh = expf(th) * c_anchors[alevel][a][1];
        size_t aidx = (size_t)b * ATOT + levelOff + rr * 3 + a;
        float* bp = &g_boxes[aidx * 4];
        bp[0] = cx - 0.5f * bw;
        bp[1] = cy - 0.5f * bh;
        bp[2] = cx + 0.5f * bw;
        bp[3] = cy + 0.5f * bh;
    }
}

// Fused pred: [L2: 361][L1: 1444][L0: 5776] = 7581 blocks, heavy first.
__global__ __launch_bounds__(256) void pred_all(
    const float* __restrict__ w10, const float* __restrict__ w11, const float* __restrict__ w12,
    const float* __restrict__ b10, const float* __restrict__ b11, const float* __restrict__ b12) {
    __shared__ float xsh[8 * 1024];  // sized for max HD
    __shared__ float psh[8 * 256];
    int b = blockIdx.x;
    if (b < 361) {
        pred_body<1024, 19>(b * 8, g_x + XOFF2, w12, b12, 21660, 32.0f, 2, xsh, psh);
    } else if (b < 361 + 1444) {
        pred_body<512, 38>((b - 361) * 8, g_x + XOFF1, w11, b11, 17328, 16.0f, 1, xsh, psh);
    } else {
        pred_body<256, 76>((b - 1805) * 8, g_x + XOFF0, w10, b10, 0, 8.0f, 0, xsh, psh);
    }
}

// ---------------- top-400 selection: 2-level radix histogram ----------------
__global__ void hist1_kernel() {
    __shared__ unsigned h[4096];
    for (int i = threadIdx.x; i < 4096; i += blockDim.x) h[i] = 0u;
    __syncthreads();
    int b = blockIdx.y;
    const float* sc = &g_scores[(size_t)b * NFLAT];
    int start = blockIdx.x * 4096;
    int end = min(start + 4096, NFLAT);
    for (int i = start + (int)threadIdx.x; i < end; i += blockDim.x) {
        float s = sc[i];
        unsigned bits = (s >= 0.05f) ? __float_as_uint(s) : 0u;
        atomicAdd(&h[bits >> 20], 1u);
    }
    __syncthreads();
    for (int i = threadIdx.x; i < 4096; i += blockDim.x)
        if (h[i]) atomicAdd(&g_hist1[b * 4096 + i], h[i]);
}

__global__ void scan1_kernel() {
    __shared__ unsigned s[1024];
    int b = blockIdx.x, tid = threadIdx.x;
    unsigned v[4], sum = 0;
#pragma unroll
    for (int j = 0; j < 4; j++) {
        v[j] = g_hist1[b * 4096 + 4095 - (tid * 4 + j)];
        sum += v[j];
    }
    s[tid] = sum;
    __syncthreads();
    for (int off = 1; off < 1024; off <<= 1) {
        unsigned t = (tid >= off) ? s[tid - off] : 0u;
        __syncthreads();
        s[tid] += t;
        __syncthreads();
    }
    unsigned excl = s[tid] - sum;
    unsigned cum = excl;
#pragma unroll
    for (int j = 0; j < 4; j++) {
        if (cum < PRE_NMS && cum + v[j] >= PRE_NMS) {
            g_b1[b] = 4095 - (tid * 4 + j);
            g_prefix1[b] = cum;
        }
        cum += v[j];
    }
}

__global__ void hist2_kernel() {
    __shared__ unsigned h[4096];
    for (int i = threadIdx.x; i < 4096; i += blockDim.x) h[i] = 0u;
    __syncthreads();
    int b = blockIdx.y;
    unsigned b1 = g_b1[b];
    const float* sc = &g_scores[(size_t)b * NFLAT];
    int start = blockIdx.x * 4096;
    int end = min(start + 4096, NFLAT);
    for (int i = start + (int)threadIdx.x; i < end; i += blockDim.x) {
        float s = sc[i];
        unsigned bits = (s >= 0.05f) ? __float_as_uint(s) : 0u;
        if ((bits >> 20) == b1) atomicAdd(&h[(bits >> 8) & 0xFFFu], 1u);
    }
    __syncthreads();
    for (int i = threadIdx.x; i < 4096; i += blockDim.x)
        if (h[i]) atomicAdd(&g_hist2[b * 4096 + i], h[i]);
}

__global__ void scan2_kernel() {
    __shared__ unsigned s[1024];
    int b = blockIdx.x, tid = threadIdx.x;
    unsigned target = PRE_NMS - g_prefix1[b];
    unsigned v[4], sum = 0;
#pragma unroll
    for (int j = 0; j < 4; j++) {
        v[j] = g_hist2[b * 4096 + 4095 - (tid * 4 + j)];
        sum += v[j];
    }
    s[tid] = sum;
    __syncthreads();
    for (int off = 1; off < 1024; off <<= 1) {
        unsigned t = (tid >= off) ? s[tid - off] : 0u;
        __syncthreads();
        s[tid] += t;
        __syncthreads();
    }
    unsigned excl = s[tid] - sum;
    unsigned cum = excl;
#pragma unroll
    for (int j = 0; j < 4; j++) {
        if (cum < target && cum + v[j] >= target) {
            g_pivot[b] = (g_b1[b] << 12) | (unsigned)(4095 - (tid * 4 + j));
        }
        cum += v[j];
    }
}

__global__ void compact_kernel() {
    int b = blockIdx.y;
    unsigned pivot = g_pivot[b];
    const float* sc = &g_scores[(size_t)b * NFLAT];
    int start = blockIdx.x * 4096;
    int end = min(start + 4096, NFLAT);
    for (int i = start + (int)threadIdx.x; i < end; i += blockDim.x) {
        float s = sc[i];
        unsigned bits = (s >= 0.05f) ? __float_as_uint(s) : 0u;
        if ((bits >> 8) >= pivot) {
            unsigned pos = atomicAdd(&g_cnt[b], 1u);
            if (pos < 8192)
                g_cand[b * 8192 + pos] =
                    ((unsigned long long)bits << 32) |
                    (unsigned long long)(0xFFFFFFFFu - (unsigned)i);
        }
    }
}

// ---------------- exact top-k sort + greedy NMS + final top-100 ----------------
__global__ __launch_bounds__(512) void nms_kernel(float* __restrict__ out) {
    constexpr int NC = 2048;
    __shared__ unsigned long long keys[NC];
    __shared__ float boSh[PRE_NMS][4];
    __shared__ float areaSh[PRE_NMS];
    __shared__ float scSh[PRE_NMS];
    __shared__ int keepSh[PRE_NMS];
    __shared__ int aiSh[PRE_NMS];
    __shared__ int ciSh[PRE_NMS];
    __shared__ unsigned long long key2[512];

    int b = blockIdx.x;
    int tid = threadIdx.x;
    int cnt = min((int)g_cnt[b], NC);
    for (int i = tid; i < NC; i += 512)
        keys[i] = (i < cnt) ? g_cand[b * 8192 + i] : 0ull;
    __syncthreads();

    for (int k = 2; k <= NC; k <<= 1) {
        for (int j = k >> 1; j > 0; j >>= 1) {
            for (int i = tid; i < NC; i += 512) {
                int ixj = i ^ j;
                if (ixj > i) {
                    bool up = ((i & k) == 0);
                    unsigned long long a = keys[i], c = keys[ixj];
                    if (up ? (a > c) : (a < c)) { keys[i] = c; keys[ixj] = a; }
                }
            }
            __syncthreads();
        }
    }

    if (tid < PRE_NMS) {
        unsigned long long key = keys[NC - 1 - tid];
        unsigned bits = (unsigned)(key >> 32);
        unsigned flat = 0xFFFFFFFFu - (unsigned)(key & 0xFFFFFFFFull);
        if (key == 0ull) { bits = 0u; flat = 0u; }
        float s = __uint_as_float(bits);
        int a = (int)(flat / NCLS);
        int c = (int)(flat % NCLS);
        const float* bp = &g_boxes[((size_t)b * ATOT + a) * 4];
        float off = (float)c * 1216.0f;
        float x0 = bp[0] + off, y0 = bp[1] + off;
        float x1 = bp[2] + off, y1 = bp[3] + off;
        boSh[tid][0] = x0; boSh[tid][1] = y0; boSh[tid][2] = x1; boSh[tid][3] = y1;
        areaSh[tid] = (x1 - x0) * (y1 - y0);
        scSh[tid] = s;
        keepSh[tid] = 1;
        aiSh[tid] = a;
        ciSh[tid] = c;
    }
    __syncthreads();

    for (int i = 0; i < PRE_NMS; i++) {
        bool act = (keepSh[i] != 0) && (scSh[i] > 0.f);
        if (act && tid > i && tid < PRE_NMS) {
            float lx = fmaxf(boSh[i][0], boSh[tid][0]);
            float ly = fmaxf(boSh[i][1], boSh[tid][1]);
            float rx = fminf(boSh[i][2], boSh[tid][2]);
            float ry = fminf(boSh[i][3], boSh[tid][3]);
            float w = fmaxf(rx - lx, 0.f), h = fmaxf(ry - ly, 0.f);
            float inter = w * h;
            float iou = inter / (areaSh[i] + areaSh[tid] - inter + 1e-7f);
            if (iou > 0.5f) keepSh[tid] = 0;
        }
        __syncthreads();
    }

    {
        unsigned long long key = 0ull;
        if (tid < PRE_NMS) {
            float fin = (keepSh[tid] && scSh[tid] > 0.f) ? scSh[tid] : 0.f;
            key = ((unsigned long long)__float_as_uint(fin) << 32) |
                  (unsigned long long)(0xFFFFFFFFu - (unsigned)tid);
        }
        key2[tid] = key;
    }
    __syncthreads();
    for (int k = 2; k <= 512; k <<= 1) {
        for (int j = k >> 1; j > 0; j >>= 1) {
            int i = tid;
            int ixj = i ^ j;
            if (ixj > i) {
                bool up = ((i & k) == 0);
                unsigned long long a = key2[i], c = key2[ixj];
                if (up ? (a > c) : (a < c)) { key2[i] = c; key2[ixj] = a; }
            }
            __syncthreads();
        }
    }

    if (tid < MAX_DET) {
        unsigned long long key = key2[511 - tid];
        unsigned sb = (unsigned)(key >> 32);
        int pos = (int)(0xFFFFFFFFu - (unsigned)(key & 0xFFFFFFFFull));
        int a = aiSh[pos], c = ciSh[pos];
        const float* bp = &g_boxes[((size_t)b * ATOT + a) * 4];
        int d = b * MAX_DET + tid;
        out[d * 4 + 0] = bp[0];
        out[d * 4 + 1] = bp[1];
        out[d * 4 + 2] = bp[2];
        out[d * 4 + 3] = bp[3];
        out[BATCH * MAX_DET * 4 + d] = __uint_as_float(sb);
        out[BATCH * MAX_DET * 4 + BATCH * MAX_DET + d] = (float)c;
    }
}

// ---------------- launcher ----------------
extern "C" void kernel_launch(void* const* d_in, const int* in_sizes, int n_in,
                              void* d_out, int out_size) {
    (void)out_size;
    const float *f0 = nullptr, *f1 = nullptr, *f2 = nullptr;
    const float *w3[3] = {}, *ga[3] = {}, *be[3] = {}, *w1[3] = {}, *b1[3] = {};
    int c256 = 0, c512 = 0, c1024 = 0, c255 = 0;
    for (int i = 0; i < n_in; i++) {
        const float* p = (const float*)d_in[i];
        switch (in_sizes[i]) {
            case 5914624: f0 = p; break;
            case 2957312: f1 = p; break;
            case 1478656: f2 = p; break;
            case 294912:  w3[0] = p; break;
            case 1179648: w3[1] = p; break;
            case 4718592: w3[2] = p; break;
            case 65280:   w1[0] = p; break;
            case 130560:  w1[1] = p; break;
            case 261120:  w1[2] = p; break;
            case 256:  if (c256++ == 0) ga[0] = p; else be[0] = p; break;
            case 512:  if (c512++ == 0) ga[1] = p; else be[1] = p; break;
            case 1024: if (c1024++ == 0) ga[2] = p; else be[2] = p; break;
            case 255:  if (c255 < 3) b1[c255++] = p; break;
        }
    }
    float* out = (float*)d_out;

    zero_misc<<<128, 256>>>();

    conv_all<<<1270, 256>>>(f0, f1, f2, w3[0], w3[1], w3[2],
                            ga[0], ga[1], ga[2], be[0], be[1], be[2]);
    pred_all<<<7581, 256>>>(w1[0], w1[1], w1[2], b1[0], b1[1], b1[2]);

    hist1_kernel<<<dim3(445, 8), 256>>>();
    scan1_kernel<<<8, 1024>>>();
    hist2_kernel<<<dim3(445, 8), 256>>>();
    scan2_kernel<<<8, 1024>>>();
    compact_kernel<<<dim3(445, 8), 256>>>();
    nms_kernel<<<8, 512>>>(out);
}

// round 14
// speedup vs baseline: 1.4614x; 1.0611x over previous
#include <cuda_runtime.h>
#include <cstddef>

// ---------------- problem constants ----------------
#define BATCH 8
#define NCLS 80
#define ATOT 22743            // 76*76*3 + 38*38*3 + 19*19*3
#define NFLAT (ATOT * NCLS)   // 1,819,440 per batch
#define PRE_NMS 400
#define MAX_DET 100

// ---------------- static scratch (no runtime allocs allowed) ----------------
// Disjoint activation regions so all three conv levels can run concurrently.
#define XOFF0 0
#define XOFF1 11829248                      // 46208*256
#define XOFF2 (11829248 + 5914624)          // + 11552*512
__device__ float g_x[11829248 + 5914624 + 2957312];  // + 2888*1024  (83MB)
// pred outputs, padded to 256 channels per pixel
#define POFF0 0
#define POFF1 11829248                      // 46208*256
#define POFF2 (11829248 + 2957312)          // + 11552*256
__device__ float g_pred[11829248 + 2957312 + 739328];  // + 2888*256 (62MB)
// padded w1 ([HD][256]) and bias ([3][256])
#define W1OFF0 0
#define W1OFF1 65536
#define W1OFF2 196608
__device__ float g_w1p[458752];
__device__ float g_b1p[3 * 256];

__device__ float g_boxes[BATCH * ATOT * 4];
__device__ float g_scores[(size_t)BATCH * NFLAT];
__device__ unsigned g_hist1[BATCH * 4096];
__device__ unsigned g_hist2[BATCH * 4096];
__device__ unsigned g_b1[BATCH];
__device__ unsigned g_prefix1[BATCH];
__device__ unsigned g_pivot[BATCH];
__device__ unsigned g_cnt[BATCH];
__device__ unsigned long long g_cand[BATCH * 8192];

__constant__ float c_anchors[3][3][2] = {
    {{12.f, 16.f}, {19.f, 36.f}, {40.f, 28.f}},
    {{36.f, 75.f}, {76.f, 55.f}, {72.f, 146.f}},
    {{142.f, 110.f}, {192.f, 243.f}, {459.f, 401.f}}};

__device__ __forceinline__ float sigmoidf_(float x) { return 1.0f / (1.0f + expf(-x)); }

// ---------------- init ----------------
__global__ void zero_misc() {
    int i = blockIdx.x * blockDim.x + threadIdx.x;
    if (i < BATCH * 4096) { g_hist1[i] = 0u; g_hist2[i] = 0u; }
    if (i < BATCH) {
        g_cnt[i] = 0u;
        g_b1[i] = 0u;
        g_prefix1[i] = 0u;
        g_pivot[i] = 0u;
    }
}

// pad w1 [HD][255] -> [HD][256] (col 255 = 0), bias [255] -> [256]
__global__ void pad_w1(const float* __restrict__ w10, const float* __restrict__ w11,
                       const float* __restrict__ w12, const float* __restrict__ b10,
                       const float* __restrict__ b11, const float* __restrict__ b12) {
    int i = blockIdx.x * blockDim.x + threadIdx.x;
    if (i < 65536) {
        int k = i >> 8, n = i & 255;
        g_w1p[W1OFF0 + i] = (n < 255) ? w10[k * 255 + n] : 0.f;
    } else if (i < 65536 + 131072) {
        int r = i - 65536;
        int k = r >> 8, n = r & 255;
        g_w1p[W1OFF1 + r] = (n < 255) ? w11[k * 255 + n] : 0.f;
    } else if (i < 458752) {
        int r = i - 196608;
        int k = r >> 8, n = r & 255;
        g_w1p[W1OFF2 + r] = (n < 255) ? w12[k * 255 + n] : 0.f;
    } else if (i < 458752 + 768) {
        int r = i - 458752;
        int l = r >> 8, n = r & 255;
        const float* bb = l == 0 ? b10 : (l == 1 ? b11 : b12);
        g_b1p[r] = (n < 255) ? bb[n] : 0.f;
    }
}

// ---------------- conv3x3 body: VERBATIM R4/R12 (proven) ----------------
template <int CIN, int COUT, int HH>
__device__ __forceinline__ void conv_body(
    int bm0, int bn0,
    const float* __restrict__ in, const float* __restrict__ w,
    const float* __restrict__ gamma, const float* __restrict__ beta,
    float* __restrict__ out,
    float (*As)[16][132], float (*Bs)[16][132]) {
    constexpr int M = BATCH * HH * HH;
    constexpr int KTOT = 9 * CIN;
    constexpr int NT = KTOT / 16;

    const int tid = threadIdx.x;

    const int kq = (tid & 3) * 4;
    int aB[2], aOy[2], aOx[2];
    bool aValid[2];
#pragma unroll
    for (int l = 0; l < 2; l++) {
        int m = l * 64 + (tid >> 2);
        int gm = bm0 + m;
        aValid[l] = (gm < M);
        int gmc = aValid[l] ? gm : 0;
        aB[l] = gmc / (HH * HH);
        int rr = gmc % (HH * HH);
        aOy[l] = rr / HH;
        aOx[l] = rr % HH;
    }
    const int bK = tid >> 5;
    const int bN = (tid & 31) * 4;

    const int ty = tid >> 4;
    const int tx = tid & 15;

    float acc[8][8] = {};
    float4 aReg[2], bReg[2];

    auto loadTile = [&](int kt) {
        const int kk = kt * 16;
        const int tap = kk / CIN;
        const int ky = tap / 3, kx = tap % 3;
        const int ciB = kk % CIN;
#pragma unroll
        for (int l = 0; l < 2; l++) {
            int iy = aOy[l] + ky - 1;
            int ix = aOx[l] + kx - 1;
            float4 v = make_float4(0.f, 0.f, 0.f, 0.f);
            if (aValid[l] && iy >= 0 && iy < HH && ix >= 0 && ix < HH)
                v = *(const float4*)&in[(((size_t)aB[l] * HH + iy) * HH + ix) * CIN + ciB + kq];
            aReg[l] = v;
            bReg[l] = *(const float4*)&w[(size_t)(kk + l * 8 + bK) * COUT + bn0 + bN];
        }
    };
    auto storeTile = [&](int buf) {
#pragma unroll
        for (int l = 0; l < 2; l++) {
            int m = l * 64 + (tid >> 2);
            As[buf][kq + 0][m] = aReg[l].x;
            As[buf][kq + 1][m] = aReg[l].y;
            As[buf][kq + 2][m] = aReg[l].z;
            As[buf][kq + 3][m] = aReg[l].w;
            *(float4*)&Bs[buf][l * 8 + bK][bN] = bReg[l];
        }
    };

    loadTile(0);
    storeTile(0);
    __syncthreads();

    for (int kt = 0; kt < NT; kt++) {
        const int buf = kt & 1;
        if (kt + 1 < NT) loadTile(kt + 1);
#pragma unroll
        for (int k = 0; k < 16; k++) {
            float4 a0 = *(float4*)&As[buf][k][ty * 4];
            float4 a1 = *(float4*)&As[buf][k][ty * 4 + 64];
            float4 b0 = *(float4*)&Bs[buf][k][tx * 4];
            float4 b1 = *(float4*)&Bs[buf][k][tx * 4 + 64];
            float av[8] = {a0.x, a0.y, a0.z, a0.w, a1.x, a1.y, a1.z, a1.w};
            float bv[8] = {b0.x, b0.y, b0.z, b0.w, b1.x, b1.y, b1.z, b1.w};
#pragma unroll
            for (int i = 0; i < 8; i++)
#pragma unroll
                for (int j = 0; j < 8; j++) acc[i][j] += av[i] * bv[j];
        }
        if (kt + 1 < NT) {
            storeTile(buf ^ 1);
            __syncthreads();
        }
    }

    float4 g0 = *(const float4*)&gamma[bn0 + tx * 4];
    float4 g1 = *(const float4*)&gamma[bn0 + tx * 4 + 64];
    float4 e0 = *(const float4*)&beta[bn0 + tx * 4];
    float4 e1 = *(const float4*)&beta[bn0 + tx * 4 + 64];
    float gv[8] = {g0.x, g0.y, g0.z, g0.w, g1.x, g1.y, g1.z, g1.w};
    float ev[8] = {e0.x, e0.y, e0.z, e0.w, e1.x, e1.y, e1.z, e1.w};
#pragma unroll
    for (int i = 0; i < 8; i++) {
        int gm = bm0 + ty * 4 + (i & 3) + (i >> 2) * 64;
        if (gm < M) {
            float t[8];
#pragma unroll
            for (int j = 0; j < 8; j++) {
                float v = acc[i][j] * gv[j] + ev[j];
                t[j] = v > 0.f ? v : 0.1f * v;
            }
            *(float4*)&out[(size_t)gm * COUT + bn0 + tx * 4] =
                make_float4(t[0], t[1], t[2], t[3]);
            *(float4*)&out[(size_t)gm * COUT + bn0 + tx * 4 + 64] =
                make_float4(t[4], t[5], t[6], t[7]);
        }
    }
}

// Fused conv: [L2: 184][L1: 364][L0: 722] = 1270 blocks, heavy first.
__global__ __launch_bounds__(256, 2) void conv_all(
    const float* __restrict__ f0, const float* __restrict__ f1, const float* __restrict__ f2,
    const float* __restrict__ w30, const float* __restrict__ w31, const float* __restrict__ w32,
    const float* __restrict__ ga0, const float* __restrict__ ga1, const float* __restrict__ ga2,
    const float* __restrict__ be0, const float* __restrict__ be1, const float* __restrict__ be2) {
    __shared__ float As[2][16][132];
    __shared__ float Bs[2][16][132];
    int b = blockIdx.x;
    if (b < 184) {
        conv_body<512, 1024, 19>((b % 23) * 128, (b / 23) * 128, f2, w32, ga2, be2,
                                 g_x + XOFF2, As, Bs);
    } else if (b < 184 + 364) {
        int r = b - 184;
        conv_body<256, 512, 38>((r % 91) * 128, (r / 91) * 128, f1, w31, ga1, be1,
                                g_x + XOFF1, As, Bs);
    } else {
        int r = b - 548;
        conv_body<128, 256, 76>((r % 361) * 128, (r / 361) * 128, f0, w30, ga0, be0,
                                g_x + XOFF0, As, Bs);
    }
}

// ---------------- pred as 1x1 GEMM (same structure, sequential-k order) ----------------
// M = pixels, N = 256 (padded), K = HD. acc + bias, no leaky, write g_pred.
template <int HD, int HH>
__device__ __forceinline__ void gemm1x1_body(
    int bm0, int bn0,
    const float* __restrict__ in, const float* __restrict__ w,
    const float* __restrict__ bias, float* __restrict__ out,
    float (*As)[16][132], float (*Bs)[16][132]) {
    constexpr int M = BATCH * HH * HH;
    constexpr int NT = HD / 16;

    const int tid = threadIdx.x;
    const int kq = (tid & 3) * 4;
    int aRow[2];
    bool aValid[2];
#pragma unroll
    for (int l = 0; l < 2; l++) {
        int gm = bm0 + l * 64 + (tid >> 2);
        aValid[l] = (gm < M);
        aRow[l] = aValid[l] ? gm : 0;
    }
    const int bK = tid >> 5;
    const int bN = (tid & 31) * 4;
    const int ty = tid >> 4;
    const int tx = tid & 15;

    float acc[8][8] = {};
    float4 aReg[2], bReg[2];

    auto loadTile = [&](int kt) {
        const int kk = kt * 16;
#pragma unroll
        for (int l = 0; l < 2; l++) {
            aReg[l] = aValid[l] ? *(const float4*)&in[(size_t)aRow[l] * HD + kk + kq]
                                : make_float4(0.f, 0.f, 0.f, 0.f);
            bReg[l] = *(const float4*)&w[(size_t)(kk + l * 8 + bK) * 256 + bn0 + bN];
        }
    };
    auto storeTile = [&](int buf) {
#pragma unroll
        for (int l = 0; l < 2; l++) {
            int m = l * 64 + (tid >> 2);
            As[buf][kq + 0][m] = aReg[l].x;
            As[buf][kq + 1][m] = aReg[l].y;
            As[buf][kq + 2][m] = aReg[l].z;
            As[buf][kq + 3][m] = aReg[l].w;
            *(float4*)&Bs[buf][l * 8 + bK][bN] = bReg[l];
        }
    };

    loadTile(0);
    storeTile(0);
    __syncthreads();
    for (int kt = 0; kt < NT; kt++) {
        const int buf = kt & 1;
        if (kt + 1 < NT) loadTile(kt + 1);
#pragma unroll
        for (int k = 0; k < 16; k++) {
            float4 a0 = *(float4*)&As[buf][k][ty * 4];
            float4 a1 = *(float4*)&As[buf][k][ty * 4 + 64];
            float4 b0 = *(float4*)&Bs[buf][k][tx * 4];
            float4 b1 = *(float4*)&Bs[buf][k][tx * 4 + 64];
            float av[8] = {a0.x, a0.y, a0.z, a0.w, a1.x, a1.y, a1.z, a1.w};
            float bv[8] = {b0.x, b0.y, b0.z, b0.w, b1.x, b1.y, b1.z, b1.w};
#pragma unroll
            for (int i = 0; i < 8; i++)
#pragma unroll
                for (int j = 0; j < 8; j++) acc[i][j] += av[i] * bv[j];
        }
        if (kt + 1 < NT) {
            storeTile(buf ^ 1);
            __syncthreads();
        }
    }

    float4 e0 = *(const float4*)&bias[bn0 + tx * 4];
    float4 e1 = *(const float4*)&bias[bn0 + tx * 4 + 64];
    float ev[8] = {e0.x, e0.y, e0.z, e0.w, e1.x, e1.y, e1.z, e1.w};
#pragma unroll
    for (int i = 0; i < 8; i++) {
        int gm = bm0 + ty * 4 + (i & 3) + (i >> 2) * 64;
        if (gm < M) {
            *(float4*)&out[(size_t)gm * 256 + bn0 + tx * 4] =
                make_float4(acc[i][0] + ev[0], acc[i][1] + ev[1],
                            acc[i][2] + ev[2], acc[i][3] + ev[3]);
            *(float4*)&out[(size_t)gm * 256 + bn0 + tx * 4 + 64] =
                make_float4(acc[i][4] + ev[4], acc[i][5] + ev[5],
                            acc[i][6] + ev[6], acc[i][7] + ev[7]);
        }
    }
}

// Fused pred GEMM: [L2: 23x2=46][L1: 91x2=182][L0: 361x2=722] = 950 blocks.
__global__ __launch_bounds__(256, 2) void pred_gemm_all() {
    __shared__ float As[2][16][132];
    __shared__ float Bs[2][16][132];
    int b = blockIdx.x;
    if (b < 46) {
        gemm1x1_body<1024, 19>((b % 23) * 128, (b / 23) * 128, g_x + XOFF2,
                               g_w1p + W1OFF2, g_b1p + 512, g_pred + POFF2, As, Bs);
    } else if (b < 46 + 182) {
        int r = b - 46;
        gemm1x1_body<512, 38>((r % 91) * 128, (r / 91) * 128, g_x + XOFF1,
                              g_w1p + W1OFF1, g_b1p + 256, g_pred + POFF1, As, Bs);
    } else {
        int r = b - 228;
        gemm1x1_body<256, 76>((r % 361) * 128, (r / 361) * 128, g_x + XOFF0,
                              g_w1p + W1OFF0, g_b1p + 0, g_pred + POFF0, As, Bs);
    }
}

// ---------------- decode: sigmoid/box math (identical formulas) ----------------
template <int HH>
__device__ __forceinline__ void decode_body(int pix0, const float* __restrict__ pin,
                                            int levelOff, float stride, int alevel,
                                            float (*psh)[256]) {
    constexpr int P = 8;
    const int tid = threadIdx.x;
    for (int id = tid; id < P * 64; id += 256) {
        int p = id >> 6;
        int r = id & 63;
        *(float4*)&psh[p][r * 4] = *(const float4*)&pin[(size_t)(pix0 + p) * 256 + r * 4];
    }
    __syncthreads();

    for (int wi = tid; wi < P * 240; wi += 256) {
        int p = wi / 240, r = wi % 240;
        int a = r / 80, c = r % 80;
        float so = sigmoidf_(psh[p][a * 85 + 4]);
        float sc = sigmoidf_(psh[p][a * 85 + 5 + c]);
        int pix = pix0 + p;
        int b = pix / (HH * HH);
        int rr = pix % (HH * HH);
        size_t aidx = (size_t)b * ATOT + levelOff + rr * 3 + a;
        g_scores[aidx * NCLS + c] = so * sc;
    }
    for (int wi = tid; wi < P * 3; wi += 256) {
        int p = wi / 3, a = wi % 3;
        int pix = pix0 + p;
        int b = pix / (HH * HH);
        int rr = pix % (HH * HH);
        int oy = rr / HH, ox = rr % HH;
        float tx = psh[p][a * 85 + 0];
        float ty = psh[p][a * 85 + 1];
        float tw = psh[p][a * 85 + 2];
        float th = psh[p][a * 85 + 3];
        float cx = ((sigmoidf_(tx) * 1.05f - 0.025f) + (float)ox) * stride;
        float cy = ((sigmoidf_(ty) * 1.05f - 0.025f) + (float)oy) * stride;
        float bw = expf(tw) * c_anchors[alevel][a][0];
        float bh = expf(th) * c_anchors[alevel][a][1];
        size_t aidx = (size_t)b * ATOT + levelOff + rr * 3 + a;
        float* bp = &g_boxes[aidx * 4];
        bp[0] = cx - 0.5f * bw;
        bp[1] = cy - 0.5f * bh;
        bp[2] = cx + 0.5f * bw;
        bp[3] = cy + 0.5f * bh;
    }
}

// [L2: 361][L1: 1444][L0: 5776] = 7581 blocks.
__global__ __launch_bounds__(256) void decode_all() {
    __shared__ float psh[8][256];
    int b = blockIdx.x;
    if (b < 361) {
        decode_body<19>(b * 8, g_pred + POFF2, 21660, 32.0f, 2, psh);
    } else if (b < 361 + 1444) {
        decode_body<38>((b - 361) * 8, g_pred + POFF1, 17328, 16.0f, 1, psh);
    } else {
        decode_body<76>((b - 1805) * 8, g_pred + POFF0, 0, 8.0f, 0, psh);
    }
}

// ---------------- top-400 selection: 2-level radix histogram ----------------
__global__ void hist1_kernel() {
    __shared__ unsigned h[4096];
    for (int i = threadIdx.x; i < 4096; i += blockDim.x) h[i] = 0u;
    __syncthreads();
    int b = blockIdx.y;
    const float* sc = &g_scores[(size_t)b * NFLAT];
    int start = blockIdx.x * 4096;
    int end = min(start + 4096, NFLAT);
    for (int i = start + (int)threadIdx.x; i < end; i += blockDim.x) {
        float s = sc[i];
        unsigned bits = (s >= 0.05f) ? __float_as_uint(s) : 0u;
        atomicAdd(&h[bits >> 20], 1u);
    }
    __syncthreads();
    for (int i = threadIdx.x; i < 4096; i += blockDim.x)
        if (h[i]) atomicAdd(&g_hist1[b * 4096 + i], h[i]);
}

__global__ void scan1_kernel() {
    __shared__ unsigned s[1024];
    int b = blockIdx.x, tid = threadIdx.x;
    unsigned v[4], sum = 0;
#pragma unroll
    for (int j = 0; j < 4; j++) {
        v[j] = g_hist1[b * 4096 + 4095 - (tid * 4 + j)];
        sum += v[j];
    }
    s[tid] = sum;
    __syncthreads();
    for (int off = 1; off < 1024; off <<= 1) {
        unsigned t = (tid >= off) ? s[tid - off] : 0u;
        __syncthreads();
        s[tid] += t;
        __syncthreads();
    }
    unsigned excl = s[tid] - sum;
    unsigned cum = excl;
#pragma unroll
    for (int j = 0; j < 4; j++) {
        if (cum < PRE_NMS && cum + v[j] >= PRE_NMS) {
            g_b1[b] = 4095 - (tid * 4 + j);
            g_prefix1[b] = cum;
        }
        cum += v[j];
    }
}

__global__ void hist2_kernel() {
    __shared__ unsigned h[4096];
    for (int i = threadIdx.x; i < 4096; i += blockDim.x) h[i] = 0u;
    __syncthreads();
    int b = blockIdx.y;
    unsigned b1 = g_b1[b];
    const float* sc = &g_scores[(size_t)b * NFLAT];
    int start = blockIdx.x * 4096;
    int end = min(start + 4096, NFLAT);
    for (int i = start + (int)threadIdx.x; i < end; i += blockDim.x) {
        float s = sc[i];
        unsigned bits = (s >= 0.05f) ? __float_as_uint(s) : 0u;
        if ((bits >> 20) == b1) atomicAdd(&h[(bits >> 8) & 0xFFFu], 1u);
    }
    __syncthreads();
    for (int i = threadIdx.x; i < 4096; i += blockDim.x)
        if (h[i]) atomicAdd(&g_hist2[b * 4096 + i], h[i]);
}

__global__ void scan2_kernel() {
    __shared__ unsigned s[1024];
    int b = blockIdx.x, tid = threadIdx.x;
    unsigned target = PRE_NMS - g_prefix1[b];
    unsigned v[4], sum = 0;
#pragma unroll
    for (int j = 0; j < 4; j++) {
        v[j] = g_hist2[b * 4096 + 4095 - (tid * 4 + j)];
        sum += v[j];
    }
    s[tid] = sum;
    __syncthreads();
    for (int off = 1; off < 1024; off <<= 1) {
        unsigned t = (tid >= off) ? s[tid - off] : 0u;
        __syncthreads();
        s[tid] += t;
        __syncthreads();
    }
    unsigned excl = s[tid] - sum;
    unsigned cum = excl;
#pragma unroll
    for (int j = 0; j < 4; j++) {
        if (cum < target && cum + v[j] >= target) {
            g_pivot[b] = (g_b1[b] << 12) | (unsigned)(4095 - (tid * 4 + j));
        }
        cum += v[j];
    }
}

__global__ void compact_kernel() {
    int b = blockIdx.y;
    unsigned pivot = g_pivot[b];
    const float* sc = &g_scores[(size_t)b * NFLAT];
    int start = blockIdx.x * 4096;
    int end = min(start + 4096, NFLAT);
    for (int i = start + (int)threadIdx.x; i < end; i += blockDim.x) {
        float s = sc[i];
        unsigned bits = (s >= 0.05f) ? __float_as_uint(s) : 0u;
        if ((bits >> 8) >= pivot) {
            unsigned pos = atomicAdd(&g_cnt[b], 1u);
            if (pos < 8192)
                g_cand[b * 8192 + pos] =
                    ((unsigned long long)bits << 32) |
                    (unsigned long long)(0xFFFFFFFFu - (unsigned)i);
        }
    }
}

// ---------------- exact top-k sort + greedy NMS + final top-100 ----------------
__global__ __launch_bounds__(512) void nms_kernel(float* __restrict__ out) {
    constexpr int NC = 2048;
    __shared__ unsigned long long keys[NC];
    __shared__ float boSh[PRE_NMS][4];
    __shared__ float areaSh[PRE_NMS];
    __shared__ float scSh[PRE_NMS];
    __shared__ int keepSh[PRE_NMS];
    __shared__ int aiSh[PRE_NMS];
    __shared__ int ciSh[PRE_NMS];
    __shared__ unsigned long long key2[512];

    int b = blockIdx.x;
    int tid = threadIdx.x;
    int cnt = min((int)g_cnt[b], NC);
    for (int i = tid; i < NC; i += 512)
        keys[i] = (i < cnt) ? g_cand[b * 8192 + i] : 0ull;
    __syncthreads();

    for (int k = 2; k <= NC; k <<= 1) {
        for (int j = k >> 1; j > 0; j >>= 1) {
            for (int i = tid; i < NC; i += 512) {
                int ixj = i ^ j;
                if (ixj > i) {
                    bool up = ((i & k) == 0);
                    unsigned long long a = keys[i], c = keys[ixj];
                    if (up ? (a > c) : (a < c)) { keys[i] = c; keys[ixj] = a; }
                }
            }
            __syncthreads();
        }
    }

    if (tid < PRE_NMS) {
        unsigned long long key = keys[NC - 1 - tid];
        unsigned bits = (unsigned)(key >> 32);
        unsigned flat = 0xFFFFFFFFu - (unsigned)(key & 0xFFFFFFFFull);
        if (key == 0ull) { bits = 0u; flat = 0u; }
        float s = __uint_as_float(bits);
        int a = (int)(flat / NCLS);
        int c = (int)(flat % NCLS);
        const float* bp = &g_boxes[((size_t)b * ATOT + a) * 4];
        float off = (float)c * 1216.0f;
        float x0 = bp[0] + off, y0 = bp[1] + off;
        float x1 = bp[2] + off, y1 = bp[3] + off;
        boSh[tid][0] = x0; boSh[tid][1] = y0; boSh[tid][2] = x1; boSh[tid][3] = y1;
        areaSh[tid] = (x1 - x0) * (y1 - y0);
        scSh[tid] = s;
        keepSh[tid] = 1;
        aiSh[tid] = a;
        ciSh[tid] = c;
    }
    __syncthreads();

    for (int i = 0; i < PRE_NMS; i++) {
        bool act = (keepSh[i] != 0) && (scSh[i] > 0.f);
        if (act && tid > i && tid < PRE_NMS) {
            float lx = fmaxf(boSh[i][0], boSh[tid][0]);
            float ly = fmaxf(boSh[i][1], boSh[tid][1]);
            float rx = fminf(boSh[i][2], boSh[tid][2]);
            float ry = fminf(boSh[i][3], boSh[tid][3]);
            float w = fmaxf(rx - lx, 0.f), h = fmaxf(ry - ly, 0.f);
            float inter = w * h;
            float iou = inter / (areaSh[i] + areaSh[tid] - inter + 1e-7f);
            if (iou > 0.5f) keepSh[tid] = 0;
        }
        __syncthreads();
    }

    {
        unsigned long long key = 0ull;
        if (tid < PRE_NMS) {
            float fin = (keepSh[tid] && scSh[tid] > 0.f) ? scSh[tid] : 0.f;
            key = ((unsigned long long)__float_as_uint(fin) << 32) |
                  (unsigned long long)(0xFFFFFFFFu - (unsigned)tid);
        }
        key2[tid] = key;
    }
    __syncthreads();
    for (int k = 2; k <= 512; k <<= 1) {
        for (int j = k >> 1; j > 0; j >>= 1) {
            int i = tid;
            int ixj = i ^ j;
            if (ixj > i) {
                bool up = ((i & k) == 0);
                unsigned long long a = key2[i], c = key2[ixj];
                if (up ? (a > c) : (a < c)) { key2[i] = c; key2[ixj] = a; }
            }
            __syncthreads();
        }
    }

    if (tid < MAX_DET) {
        unsigned long long key = key2[511 - tid];
        unsigned sb = (unsigned)(key >> 32);
        int pos = (int)(0xFFFFFFFFu - (unsigned)(key & 0xFFFFFFFFull));
        int a = aiSh[pos], c = ciSh[pos];
        const float* bp = &g_boxes[((size_t)b * ATOT + a) * 4];
        int d = b * MAX_DET + tid;
        out[d * 4 + 0] = bp[0];
        out[d * 4 + 1] = bp[1];
        out[d * 4 + 2] = bp[2];
        out[d * 4 + 3] = bp[3];
        out[BATCH * MAX_DET * 4 + d] = __uint_as_float(sb);
        out[BATCH * MAX_DET * 4 + BATCH * MAX_DET + d] = (float)c;
    }
}

// ---------------- launcher ----------------
extern "C" void kernel_launch(void* const* d_in, const int* in_sizes, int n_in,
                              void* d_out, int out_size) {
    (void)out_size;
    const float *f0 = nullptr, *f1 = nullptr, *f2 = nullptr;
    const float *w3[3] = {}, *ga[3] = {}, *be[3] = {}, *w1[3] = {}, *b1[3] = {};
    int c256 = 0, c512 = 0, c1024 = 0, c255 = 0;
    for (int i = 0; i < n_in; i++) {
        const float* p = (const float*)d_in[i];
        switch (in_sizes[i]) {
            case 5914624: f0 = p; break;
            case 2957312: f1 = p; break;
            case 1478656: f2 = p; break;
            case 294912:  w3[0] = p; break;
            case 1179648: w3[1] = p; break;
            case 4718592: w3[2] = p; break;
            case 65280:   w1[0] = p; break;
            case 130560:  w1[1] = p; break;
            case 261120:  w1[2] = p; break;
            case 256:  if (c256++ == 0) ga[0] = p; else be[0] = p; break;
            case 512:  if (c512++ == 0) ga[1] = p; else be[1] = p; break;
            case 1024: if (c1024++ == 0) ga[2] = p; else be[2] = p; break;
            case 255:  if (c255 < 3) b1[c255++] = p; break;
        }
    }
    float* out = (float*)d_out;

    zero_misc<<<128, 256>>>();
    pad_w1<<<1796, 256>>>(w1[0], w1[1], w1[2], b1[0], b1[1], b1[2]);

    conv_all<<<1270, 256>>>(f0, f1, f2, w3[0], w3[1], w3[2],
                            ga[0], ga[1], ga[2], be[0], be[1], be[2]);
    pred_gemm_all<<<950, 256>>>();
    decode_all<<<7581, 256>>>();

    hist1_kernel<<<dim3(445, 8), 256>>>();
    scan1_kernel<<<8, 1024>>>();
    hist2_kernel<<<dim3(445, 8), 256>>>();
    scan2_kernel<<<8, 1024>>>();
    compact_kernel<<<dim3(445, 8), 256>>>();
    nms_kernel<<<8, 512>>>(out);
}